// round 2
// baseline (speedup 1.0000x reference)
#include <cuda_runtime.h>

#define BUF 4194304u
__device__ float g_scratch[5u * BUF];

// ---------------- SGEMM 128x128x8, M=4096 N=1024 K=1024 ----------------
__global__ __launch_bounds__(256, 2)
void sgemm128(const float* __restrict__ A, const float* __restrict__ B,
              const float* __restrict__ R, float* __restrict__ C) {
    __shared__ float As[8][128];
    __shared__ float Bs[8][128];
    const int t = threadIdx.x;
    const int n0 = blockIdx.x * 128, m0 = blockIdx.y * 128;
    const int tx = t & 15, ty = t >> 4;
    const int arow = t >> 1, acol = (t & 1) * 4;
    const int brow = t >> 5, bcol = (t & 31) * 4;
    const float* Ap = A + (size_t)(m0 + arow) * 1024 + acol;
    const float* Bp = B + (size_t)brow * 1024 + n0 + bcol;

    float acc[8][8];
#pragma unroll
    for (int i = 0; i < 8; i++)
#pragma unroll
        for (int j = 0; j < 8; j++) acc[i][j] = 0.f;

    for (int kb = 0; kb < 1024; kb += 8) {
        float4 av = *(const float4*)(Ap + kb);
        float4 bv = *(const float4*)(Bp + (size_t)kb * 1024);
        __syncthreads();
        As[acol + 0][arow] = av.x; As[acol + 1][arow] = av.y;
        As[acol + 2][arow] = av.z; As[acol + 3][arow] = av.w;
        *(float4*)&Bs[brow][bcol] = bv;
        __syncthreads();
#pragma unroll
        for (int k = 0; k < 8; k++) {
            float a[8], b[8];
            *(float4*)&a[0] = *(const float4*)&As[k][ty * 8];
            *(float4*)&a[4] = *(const float4*)&As[k][ty * 8 + 4];
            *(float4*)&b[0] = *(const float4*)&Bs[k][tx * 8];
            *(float4*)&b[4] = *(const float4*)&Bs[k][tx * 8 + 4];
#pragma unroll
            for (int i = 0; i < 8; i++)
#pragma unroll
                for (int j = 0; j < 8; j++) acc[i][j] += a[i] * b[j];
        }
    }
#pragma unroll
    for (int i = 0; i < 8; i++) {
        const int m = m0 + ty * 8 + i;
        float* cp = C + (size_t)m * 1024 + n0 + tx * 8;
        float4 o0 = make_float4(acc[i][0], acc[i][1], acc[i][2], acc[i][3]);
        float4 o1 = make_float4(acc[i][4], acc[i][5], acc[i][6], acc[i][7]);
        if (R) {
            const float* rp = R + (size_t)m * 1024 + n0 + tx * 8;
            float4 r0 = *(const float4*)rp, r1 = *(const float4*)(rp + 4);
            o0.x += r0.x; o0.y += r0.y; o0.z += r0.z; o0.w += r0.w;
            o1.x += r1.x; o1.y += r1.y; o1.z += r1.z; o1.w += r1.w;
        }
        *(float4*)cp = o0; *(float4*)(cp + 4) = o1;
    }
}

// ---------------- fused attention, softmax over HEADS ----------------
// smem: Qs/Ks/Vs [(h*16+row)*65 + d] (16640 floats each), sc [q*273 + k*17 + h]
#define SM_Q 0
#define SM_K 16640
#define SM_V 33280
#define SM_S 49920
#define SM_FLOATS (49920 + 4368)
#define SM_BYTES (SM_FLOATS * 4)

__device__ __forceinline__ void stage_tile(const float* __restrict__ src,
                                           float* __restrict__ dst, int t) {
    const int r = t >> 4, c4 = t & 15;
#pragma unroll
    for (int it = 0; it < 16; it++) {
        float4 v = *(const float4*)(src + (size_t)r * 1024 + c4 * 4 + 64 * it);
        float* d = &dst[(it * 16 + r) * 65 + c4 * 4];
        d[0] = v.x; d[1] = v.y; d[2] = v.z; d[3] = v.w;
    }
}

__global__ __launch_bounds__(256, 1)
void attn_kernel(const float* __restrict__ Q, const float* __restrict__ K,
                 const float* __restrict__ V, float* __restrict__ Ctx) {
    extern __shared__ float sm[];
    const int t = threadIdx.x;
    const int b = blockIdx.y;
    const int q0g = blockIdx.x << 4;

    const float* Qb = Q + ((size_t)b * 2048 + q0g) * 1024;
    const float* Kb = K + (size_t)b * 2048 * 1024;
    const float* Vb = V + (size_t)b * 2048 * 1024;

    stage_tile(Qb, sm + SM_Q, t);

    const int h  = t >> 4;
    const int w  = t & 15;
    const int sq0 = (w >> 2) * 4, sk0 = (w & 3) * 4;   // scores block
    const int cq0 = (w >> 2) * 4, vb = (w & 3);        // ctx block (v stride 4)
    const int sxq = t >> 4, sxk = t & 15;              // softmax pair

    float cacc[4][16];
#pragma unroll
    for (int i = 0; i < 4; i++)
#pragma unroll
        for (int j = 0; j < 16; j++) cacc[i][j] = 0.f;

    for (int kt = 0; kt < 128; kt++) {
        __syncthreads();
        stage_tile(Kb + (size_t)kt * 16 * 1024, sm + SM_K, t);
        stage_tile(Vb + (size_t)kt * 16 * 1024, sm + SM_V, t);
        __syncthreads();

        // scores: 4q x 4k per thread
        {
            float a4[4][4];
#pragma unroll
            for (int i = 0; i < 4; i++)
#pragma unroll
                for (int j = 0; j < 4; j++) a4[i][j] = 0.f;
            const float* qp = &sm[SM_Q + (h * 16 + sq0) * 65];
            const float* kp = &sm[SM_K + (h * 16 + sk0) * 65];
#pragma unroll 8
            for (int d = 0; d < 64; d++) {
                float qv[4], kv[4];
#pragma unroll
                for (int i = 0; i < 4; i++) qv[i] = qp[i * 65 + d];
#pragma unroll
                for (int j = 0; j < 4; j++) kv[j] = kp[j * 65 + d];
#pragma unroll
                for (int i = 0; i < 4; i++)
#pragma unroll
                    for (int j = 0; j < 4; j++) a4[i][j] += qv[i] * kv[j];
            }
#pragma unroll
            for (int i = 0; i < 4; i++)
#pragma unroll
                for (int j = 0; j < 4; j++)
                    sm[SM_S + (sq0 + i) * 273 + (sk0 + j) * 17 + h] = a4[i][j] * 0.125f;
        }
        __syncthreads();

        // softmax over heads for one (q,k)
        {
            float* p = &sm[SM_S + sxq * 273 + sxk * 17];
            float m = p[0];
#pragma unroll
            for (int hh = 1; hh < 16; hh++) m = fmaxf(m, p[hh]);
            float s = 0.f;
#pragma unroll
            for (int hh = 0; hh < 16; hh++) { float e = __expf(p[hh] - m); p[hh] = e; s += e; }
            float inv = 1.f / s;
#pragma unroll
            for (int hh = 0; hh < 16; hh++) p[hh] *= inv;
        }
        __syncthreads();

        // context: 4q x 16v per thread
#pragma unroll 4
        for (int k = 0; k < 16; k++) {
            float av[4];
#pragma unroll
            for (int i = 0; i < 4; i++)
                av[i] = sm[SM_S + (cq0 + i) * 273 + k * 17 + h];
            const float* vr = &sm[SM_V + (h * 16 + k) * 65 + vb];
#pragma unroll
            for (int vi = 0; vi < 16; vi++) {
                float vv = vr[vi * 4];
#pragma unroll
                for (int i = 0; i < 4; i++) cacc[i][vi] += av[i] * vv;
            }
        }
    }

#pragma unroll
    for (int i = 0; i < 4; i++)
#pragma unroll
        for (int vi = 0; vi < 16; vi++)
            Ctx[((size_t)b * 2048 + q0g + cq0 + i) * 1024 + h * 64 + vb + 4 * vi] = cacc[i][vi];
}

// ---------------- LayerNorm over last dim (1024) ----------------
__global__ __launch_bounds__(256)
void ln_kernel(const float* __restrict__ x, const float* __restrict__ gamma,
               const float* __restrict__ beta, float* __restrict__ out) {
    __shared__ float red[16];
    const int row = blockIdx.x, t = threadIdx.x;
    float4 v = ((const float4*)(x + (size_t)row * 1024))[t];
    float s = v.x + v.y + v.z + v.w;
    float q = v.x * v.x + v.y * v.y + v.z * v.z + v.w * v.w;
#pragma unroll
    for (int o = 16; o > 0; o >>= 1) {
        s += __shfl_xor_sync(0xffffffffu, s, o);
        q += __shfl_xor_sync(0xffffffffu, q, o);
    }
    if ((t & 31) == 0) { red[t >> 5] = s; red[8 + (t >> 5)] = q; }
    __syncthreads();
    if (t < 8) { s = red[t]; q = red[8 + t]; }
    if (t < 8) {
#pragma unroll
        for (int o = 4; o > 0; o >>= 1) {
            s += __shfl_xor_sync(0xffu, s, o);
            q += __shfl_xor_sync(0xffu, q, o);
        }
        if (t == 0) { red[0] = s; red[1] = q; }
    }
    __syncthreads();
    const float mu = red[0] * (1.f / 1024.f);
    const float var = red[1] * (1.f / 1024.f) - mu * mu;
    const float inv = rsqrtf(var + 1e-5f);
    float4 g = ((const float4*)gamma)[t];
    float4 bb = ((const float4*)beta)[t];
    float4 o;
    o.x = (v.x - mu) * inv * g.x + bb.x;
    o.y = (v.y - mu) * inv * g.y + bb.y;
    o.z = (v.z - mu) * inv * g.z + bb.z;
    o.w = (v.w - mu) * inv * g.w + bb.w;
    ((float4*)(out + (size_t)row * 1024))[t] = o;
}

// ---------------- launch ----------------
extern "C" void kernel_launch(void* const* d_in, const int* in_sizes, int n_in,
                              void* d_out, int out_size) {
    const float* inQ = (const float*)d_in[0];
    const float* inK = (const float*)d_in[1];
    const float* inV = (const float*)d_in[2];
    const float* WQ  = (const float*)d_in[3];
    const float* WK  = (const float*)d_in[4];
    const float* WV  = (const float*)d_in[5];
    const float* WO  = (const float*)d_in[6];
    const float* gam = (const float*)d_in[7];
    const float* bet = (const float*)d_in[8];
    float* out = (float*)d_out;

    float* base = nullptr;
    cudaGetSymbolAddress((void**)&base, g_scratch);
    float* Qb  = base;
    float* Kb  = base + BUF;
    float* Vb  = base + 2 * BUF;
    float* Cx  = base + 3 * BUF;
    float* Xb  = base + 4 * BUF;

    dim3 gg(8, 32);
    sgemm128<<<gg, 256>>>(inQ, WQ, nullptr, Qb);
    sgemm128<<<gg, 256>>>(inK, WK, nullptr, Kb);
    sgemm128<<<gg, 256>>>(inV, WV, nullptr, Vb);

    cudaFuncSetAttribute(attn_kernel, cudaFuncAttributeMaxDynamicSharedMemorySize, SM_BYTES);
    attn_kernel<<<dim3(128, 2), 256, SM_BYTES>>>(Qb, Kb, Vb, Cx);

    sgemm128<<<gg, 256>>>(Cx, WO, inQ, Xb);
    ln_kernel<<<4096, 256>>>(Xb, gam, bet, out);
}